// round 12
// baseline (speedup 1.0000x reference)
#include <cuda_runtime.h>
#include <cstdint>

// Problem constants
static constexpr int NB = 16;
static constexpr int NC = 256;
static constexpr int NH = 64;
static constexpr int NW = 64;
static constexpr int NP = 9;
static constexpr int DISP = 4;

// Tiling (R8 skeleton)
static constexpr int TI = 4;
static constexpr int CH = 8;
static constexpr int NSTAGE = NC / CH;        // 32
static constexpr int YROWS = TI + 2 * DISP;   // 12
static constexpr int PITCH = 384;
static constexpr int XAREA = CH * TI * PITCH;     // 12288
static constexpr int YAREA = CH * YROWS * PITCH;  // 36864
static constexpr int BUF = XAREA + YAREA;         // 49152
static constexpr int NTHREADS = 288;              // 9 warps, warp = di
static constexpr int NROWS = CH * YROWS + CH * TI; // 128
static constexpr int STAGE_BYTES = CH * NH * NW * 4; // 131072
static constexpr int ROWB = NW * 4;               // 256B per bulk copy

// smem: fA[2] at 0,8 ; fB[2] at 16,24 ; buffers at 128
static constexpr int BUF0 = 128;
static constexpr int SMEM_TOTAL = BUF0 + 2 * BUF; // 98432 -> 2 CTAs/SM

__device__ __forceinline__ unsigned skew(int r) {
    return ((r & 1) << 4) + ((r & 2) << 5);
}
__device__ __forceinline__ void upk(unsigned long long v, float& lo, float& hi) {
    asm("mov.b64 {%0, %1}, %2;" : "=f"(lo), "=f"(hi) : "l"(v));
}
__device__ __forceinline__ unsigned long long pk(float lo, float hi) {
    unsigned long long r;
    asm("mov.b64 %0, {%1, %2};" : "=l"(r) : "f"(lo), "f"(hi));
    return r;
}
__device__ __forceinline__ void fma2(unsigned long long& acc,
                                     unsigned long long a, unsigned long long b) {
    asm("fma.rn.f32x2 %0, %1, %2, %0;" : "+l"(acc) : "l"(a), "l"(b));
}
__device__ __forceinline__ void lds2(unsigned addr,
                                     unsigned long long& a, unsigned long long& b) {
    asm volatile("ld.shared.v2.b64 {%0, %1}, [%2];"
                 : "=l"(a), "=l"(b) : "r"(addr));
}
__device__ __forceinline__ void mbar_init(unsigned addr, unsigned count) {
    asm volatile("mbarrier.init.shared.b64 [%0], %1;" :: "r"(addr), "r"(count) : "memory");
}
__device__ __forceinline__ void mbar_expect(unsigned addr, unsigned bytes) {
    asm volatile("mbarrier.arrive.expect_tx.shared.b64 _, [%0], %1;"
                 :: "r"(addr), "r"(bytes) : "memory");
}
__device__ __forceinline__ void mbar_wait(unsigned addr, unsigned parity) {
    asm volatile(
        "{\n\t"
        ".reg .pred P;\n\t"
        "WL_%=:\n\t"
        "mbarrier.try_wait.parity.acquire.cta.shared::cta.b64 P, [%0], %1, 0x989680;\n\t"
        "@P bra.uni WD_%=;\n\t"
        "bra.uni WL_%=;\n\t"
        "WD_%=:\n\t"
        "}"
        :: "r"(addr), "r"(parity) : "memory");
}
__device__ __forceinline__ void bulk_g2s(unsigned dst, const void* src,
                                         unsigned bytes, unsigned mbar) {
    asm volatile(
        "cp.async.bulk.shared::cta.global.mbarrier::complete_tx::bytes "
        "[%0], [%1], %2, [%3];"
        :: "r"(dst), "l"(src), "r"(bytes), "r"(mbar) : "memory");
}

struct Acc {
    unsigned long long E[5][4];
    unsigned long long O[4][3];
    float sA[4], sB[4];
};

// One channel's math (R8 inner body, verbatim).
__device__ __forceinline__ void chan(unsigned xp, unsigned yp, Acc& a) {
    unsigned long long X[4], W[8];
    lds2(xp,      X[0], X[1]);
    lds2(xp + 16, X[2], X[3]);
    lds2(yp,      W[0], W[1]);
    lds2(yp + 16, W[2], W[3]);
    lds2(yp + 32, W[4], W[5]);
    lds2(yp + 48, W[6], W[7]);

    float x0, x1, x2, x3, x4, x5, x6, x7;
    upk(X[0], x0, x1); upk(X[1], x2, x3);
    upk(X[2], x4, x5); upk(X[3], x6, x7);
    unsigned long long Sx[3] = {pk(x1, x2), pk(x3, x4), pk(x5, x6)};

#pragma unroll
    for (int e = 0; e < 5; ++e)
#pragma unroll
        for (int m = 0; m < 4; ++m)
            fma2(a.E[e][m], X[m], W[m + e]);

#pragma unroll
    for (int o = 0; o < 4; ++o) {
#pragma unroll
        for (int m = 0; m < 3; ++m)
            fma2(a.O[o][m], Sx[m], W[m + 1 + o]);
        float wl, wh, vl, vh;
        upk(W[o], wl, wh);
        upk(W[4 + o], vl, vh);
        a.sA[o] = fmaf(x0, wh, a.sA[o]);
        a.sB[o] = fmaf(x7, vl, a.sB[o]);
    }
}

__global__ void __launch_bounds__(NTHREADS, 2)
corr_kernel(const float* __restrict__ x, const float* __restrict__ y,
            float* __restrict__ out) {
    extern __shared__ char smem[];
    unsigned sm32;
    asm("{ .reg .u64 t; cvta.to.shared.u64 t, %1; cvt.u32.u64 %0, t; }"
        : "=r"(sm32) : "l"(smem));

    const int tid  = threadIdx.x;
    const int di   = tid >> 5;       // warp = displacement row 0..8
    const int lane = tid & 31;
    const int jg   = lane >> 2;
    const int ti   = lane & 3;
    const int i0   = blockIdx.x * TI;
    const int b    = blockIdx.y;

    // Zero both buffers (halo cols / OOB rows stay zero forever).
    for (int o = tid * 16; o < 2 * BUF; o += NTHREADS * 16)
        *reinterpret_cast<float4*>(smem + BUF0 + o) = make_float4(0.f, 0.f, 0.f, 0.f);

    if (tid == 0) {
        mbar_init(sm32 + 0,  1);   // fA[0] : channels 0-3
        mbar_init(sm32 + 8,  1);   // fA[1]
        mbar_init(sm32 + 16, 1);   // fB[0] : channels 4-7
        mbar_init(sm32 + 24, 1);   // fB[1]
    }
    __syncthreads();
    asm volatile("fence.proxy.async.shared::cta;" ::: "memory");

    // Valid bytes PER HALF (4 channels of y rows + 4 channels of x rows).
    const int lo = (4 - i0) > 0 ? (4 - i0) : 0;
    const int hi = (i0 - 56) > 0 ? (i0 - 56) : 0;
    const unsigned BYTESH = (unsigned)((4 * (YROWS - lo - hi) + 4 * TI) * ROWB);

    // Row-owner precompute: thread k < 128 owns row k; half = (cc >= 4).
    const char* src0 = nullptr;
    unsigned dsto = 0;
    unsigned hoff = 0;            // 0 -> fA, 16 -> fB
    bool valid = false;
    if (tid < NROWS) {
        const int k = tid;
        if (k < CH * YROWS) {
            const int cc = k / YROWS;
            const int rr = k - cc * YROWS;
            const int gy = i0 - DISP + rr;
            valid = ((unsigned)gy < (unsigned)NH);
            if (valid)
                src0 = reinterpret_cast<const char*>(
                    y + (((size_t)(b * NC + cc) * NH + gy) * NW));
            dsto = XAREA + cc * (YROWS * PITCH) + rr * PITCH + skew(rr) + 16;
            hoff = (cc >= 4) ? 16u : 0u;
        } else {
            const int j  = k - CH * YROWS;
            const int cc = j >> 2;
            const int rr = j & 3;
            valid = true;
            src0 = reinterpret_cast<const char*>(
                x + (((size_t)(b * NC + cc) * NH + (i0 + rr)) * NW));
            dsto = cc * (TI * PITCH) + rr * PITCH + skew(rr);
            hoff = (cc >= 4) ? 16u : 0u;
        }
    }

    // Prologue: tid0 arms all four half-barriers; then owners issue stages 0,1.
    if (tid == 0) {
        mbar_expect(sm32 + 0,  BYTESH);
        mbar_expect(sm32 + 8,  BYTESH);
        mbar_expect(sm32 + 16, BYTESH);
        mbar_expect(sm32 + 24, BYTESH);
    }
    __syncthreads();   // expects registered before any completion can land
    if (valid) {
        bulk_g2s(sm32 + BUF0 + dsto, src0, ROWB, sm32 + hoff + 0);
        bulk_g2s(sm32 + BUF0 + BUF + dsto, src0 + STAGE_BYTES, ROWB,
                 sm32 + hoff + 8);
    }

    Acc a;
#pragma unroll
    for (int e = 0; e < 5; ++e)
#pragma unroll
        for (int m = 0; m < 4; ++m) a.E[e][m] = 0ull;
#pragma unroll
    for (int o = 0; o < 4; ++o) {
#pragma unroll
        for (int m = 0; m < 3; ++m) a.O[o][m] = 0ull;
        a.sA[o] = 0.f; a.sB[o] = 0.f;
    }

    const int r = ti + di;
    const unsigned xoff = sm32 + BUF0 + (unsigned)(ti * PITCH) + skew(ti) + jg * 32;
    const unsigned yoff = sm32 + BUF0 + (unsigned)XAREA
                        + (unsigned)(r * PITCH) + skew(r) + jg * 32;
    const bool evenw = ((di & 1) == 0);

    for (int s = 0; s < NSTAGE; ++s) {
        const unsigned bsel = (unsigned)((s & 1) * 8);
        const unsigned par  = (unsigned)((s >> 1) & 1);
        const unsigned bo   = (unsigned)((s & 1) * BUF);
        const unsigned fa   = sm32 + bsel;        // fA[s&1]
        const unsigned fb   = sm32 + 16 + bsel;   // fB[s&1]
        const bool rearm = (s + 2 < NSTAGE);

        if (evenw) {
            mbar_wait(fa, par);
            if (tid == 0 && rearm) mbar_expect(fa, BYTESH);
#pragma unroll
            for (int cc = 0; cc < 4; ++cc)
                chan(bo + (unsigned)(cc * (TI * PITCH)) + xoff,
                     bo + (unsigned)(cc * (YROWS * PITCH)) + yoff, a);
            mbar_wait(fb, par);
            if (tid == 0 && rearm) mbar_expect(fb, BYTESH);
#pragma unroll
            for (int cc = 4; cc < 8; ++cc)
                chan(bo + (unsigned)(cc * (TI * PITCH)) + xoff,
                     bo + (unsigned)(cc * (YROWS * PITCH)) + yoff, a);
        } else {
            mbar_wait(fb, par);
#pragma unroll
            for (int cc = 7; cc >= 4; --cc)
                chan(bo + (unsigned)(cc * (TI * PITCH)) + xoff,
                     bo + (unsigned)(cc * (YROWS * PITCH)) + yoff, a);
            mbar_wait(fa, par);
#pragma unroll
            for (int cc = 3; cc >= 0; --cc)
                chan(bo + (unsigned)(cc * (TI * PITCH)) + xoff,
                     bo + (unsigned)(cc * (YROWS * PITCH)) + yoff, a);
        }

        __syncthreads();   // everyone finished reading buffer (s&1)
        if (valid && rearm) {
            bulk_g2s(sm32 + BUF0 + bo + dsto,
                     src0 + (size_t)(s + 2) * STAGE_BYTES, ROWB,
                     sm32 + hoff + bsel);
        }
    }

    // ---- epilogue: scale by 1/C and store ----
    const float sc = 1.0f / (float)NC;
    float* obase = out + (((size_t)b * (NP * NP) + (size_t)di * NP) * NH
                          + (i0 + ti)) * NW + jg * 8;
#pragma unroll
    for (int e = 0; e < 5; ++e) {
        float* op = obase + (size_t)(2 * e) * NH * NW;
        float4 v;
        upk(a.E[e][0], v.x, v.y); upk(a.E[e][1], v.z, v.w);
        v.x *= sc; v.y *= sc; v.z *= sc; v.w *= sc;
        *reinterpret_cast<float4*>(op) = v;
        upk(a.E[e][2], v.x, v.y); upk(a.E[e][3], v.z, v.w);
        v.x *= sc; v.y *= sc; v.z *= sc; v.w *= sc;
        *reinterpret_cast<float4*>(op + 4) = v;
    }
#pragma unroll
    for (int o = 0; o < 4; ++o) {
        float* op = obase + (size_t)(2 * o + 1) * NH * NW;
        float f1, f2, f3, f4, f5, f6;
        upk(a.O[o][0], f1, f2);
        upk(a.O[o][1], f3, f4);
        upk(a.O[o][2], f5, f6);
        float4 v;
        v.x = a.sA[o] * sc; v.y = f1 * sc; v.z = f2 * sc; v.w = f3 * sc;
        *reinterpret_cast<float4*>(op) = v;
        v.x = f4 * sc; v.y = f5 * sc; v.z = f6 * sc; v.w = a.sB[o] * sc;
        *reinterpret_cast<float4*>(op + 4) = v;
    }
}

extern "C" void kernel_launch(void* const* d_in, const int* in_sizes, int n_in,
                              void* d_out, int out_size) {
    const float* x = (const float*)d_in[0];
    const float* y = (const float*)d_in[1];
    float* out = (float*)d_out;
    (void)in_sizes; (void)n_in; (void)out_size;

    cudaFuncSetAttribute(corr_kernel,
                         cudaFuncAttributeMaxDynamicSharedMemorySize, SMEM_TOTAL);

    dim3 grid(NH / TI, NB);   // (16, 16) = 256 blocks
    corr_kernel<<<grid, NTHREADS, SMEM_TOTAL>>>(x, y, out);
}

// round 13
// speedup vs baseline: 1.2811x; 1.2811x over previous
#include <cuda_runtime.h>
#include <cstdint>

// Problem constants
static constexpr int NB = 16;
static constexpr int NC = 256;
static constexpr int NH = 64;
static constexpr int NW = 64;
static constexpr int NP = 9;
static constexpr int DISP = 4;

// Tiling: TI=2 rows per CTA -> small regs/smem -> 3 CTAs/SM (27 warps)
static constexpr int TI = 2;
static constexpr int CH = 8;
static constexpr int NSTAGE = NC / CH;        // 32
static constexpr int YROWS = TI + 2 * DISP;   // 10
static constexpr int PITCH = 384;
static constexpr int XAREA = CH * TI * PITCH;     // 6144
static constexpr int YAREA = CH * YROWS * PITCH;  // 30720
static constexpr int BUF = XAREA + YAREA;         // 36864
static constexpr int NTHREADS = 288;              // 9 warps, warp = di
static constexpr int NROWS = CH * YROWS + CH * TI; // 80 y + 16 x = 96
static constexpr int STAGE_BYTES = CH * NH * NW * 4; // 131072
static constexpr int ROWB = NW * 4;               // 256B per bulk copy

// smem: full[2] mbarriers at 0,8; buffers at 128
static constexpr int BUF0 = 128;
static constexpr int SMEM_TOTAL = BUF0 + 2 * BUF; // 73856 -> 3 CTAs/SM

// Row skew: alternate rows by 64B so 2-row x 4-jg phases hit 8 distinct
// 16B bank groups ({0,64,16,80,32,96,48,112} mod 128 - verified).
__device__ __forceinline__ unsigned skew(int r) {
    return (unsigned)((r & 1) << 6);
}
__device__ __forceinline__ void upk(unsigned long long v, float& lo, float& hi) {
    asm("mov.b64 {%0, %1}, %2;" : "=f"(lo), "=f"(hi) : "l"(v));
}
__device__ __forceinline__ unsigned long long pk(float lo, float hi) {
    unsigned long long r;
    asm("mov.b64 %0, {%1, %2};" : "=l"(r) : "f"(lo), "f"(hi));
    return r;
}
__device__ __forceinline__ void fma2(unsigned long long& acc,
                                     unsigned long long a, unsigned long long b) {
    asm("fma.rn.f32x2 %0, %1, %2, %0;" : "+l"(acc) : "l"(a), "l"(b));
}
__device__ __forceinline__ void lds2(unsigned addr,
                                     unsigned long long& a, unsigned long long& b) {
    asm volatile("ld.shared.v2.b64 {%0, %1}, [%2];"
                 : "=l"(a), "=l"(b) : "r"(addr));
}
__device__ __forceinline__ void mbar_init(unsigned addr, unsigned count) {
    asm volatile("mbarrier.init.shared.b64 [%0], %1;" :: "r"(addr), "r"(count) : "memory");
}
__device__ __forceinline__ void mbar_expect(unsigned addr, unsigned bytes) {
    asm volatile("mbarrier.arrive.expect_tx.shared.b64 _, [%0], %1;"
                 :: "r"(addr), "r"(bytes) : "memory");
}
__device__ __forceinline__ void mbar_wait(unsigned addr, unsigned parity) {
    asm volatile(
        "{\n\t"
        ".reg .pred P;\n\t"
        "WL_%=:\n\t"
        "mbarrier.try_wait.parity.acquire.cta.shared::cta.b64 P, [%0], %1, 0x989680;\n\t"
        "@P bra.uni WD_%=;\n\t"
        "bra.uni WL_%=;\n\t"
        "WD_%=:\n\t"
        "}"
        :: "r"(addr), "r"(parity) : "memory");
}
__device__ __forceinline__ void bulk_g2s(unsigned dst, const void* src,
                                         unsigned bytes, unsigned mbar) {
    asm volatile(
        "cp.async.bulk.shared::cta.global.mbarrier::complete_tx::bytes "
        "[%0], [%1], %2, [%3];"
        :: "r"(dst), "l"(src), "r"(bytes), "r"(mbar) : "memory");
}

__global__ void __launch_bounds__(NTHREADS, 3)
corr_kernel(const float* __restrict__ x, const float* __restrict__ y,
            float* __restrict__ out) {
    extern __shared__ char smem[];
    unsigned sm32;
    asm("{ .reg .u64 t; cvta.to.shared.u64 t, %1; cvt.u32.u64 %0, t; }"
        : "=r"(sm32) : "l"(smem));

    const int tid  = threadIdx.x;
    const int di   = tid >> 5;       // warp = displacement row 0..8
    const int lane = tid & 31;
    const int jg   = lane >> 1;      // 0..15 : group of 4 output columns
    const int ti   = lane & 1;       // 0..1  : i-row in tile
    const int i0   = blockIdx.x * TI;
    const int b    = blockIdx.y;

    // Zero both buffers (halo cols / OOB rows stay zero forever).
    for (int o = tid * 16; o < 2 * BUF; o += NTHREADS * 16)
        *reinterpret_cast<float4*>(smem + BUF0 + o) = make_float4(0.f, 0.f, 0.f, 0.f);

    if (tid == 0) {
        mbar_init(sm32 + 0, 1);   // full[0]
        mbar_init(sm32 + 8, 1);   // full[1]
    }
    __syncthreads();
    asm volatile("fence.proxy.async.shared::cta;" ::: "memory");

    // Valid bytes per stage (OOB y rows never copied).
    const int lo = (DISP - i0) > 0 ? (DISP - i0) : 0;
    const int hi = (i0 + TI - 1 + DISP - (NH - 1)) > 0
                   ? (i0 + TI - 1 + DISP - (NH - 1)) : 0;
    const unsigned BYTES = (unsigned)((CH * (YROWS - lo - hi) + CH * TI) * ROWB);

    // Row-owner precompute: thread k < 96 owns row k (one 256B bulk per stage).
    const char* src0 = nullptr;
    unsigned dsto = 0;
    bool valid = false;
    if (tid < NROWS) {
        const int k = tid;
        if (k < CH * YROWS) {
            const int cc = k / YROWS;
            const int rr = k - cc * YROWS;
            const int gy = i0 - DISP + rr;
            valid = ((unsigned)gy < (unsigned)NH);
            if (valid)
                src0 = reinterpret_cast<const char*>(
                    y + (((size_t)(b * NC + cc) * NH + gy) * NW));
            dsto = XAREA + cc * (YROWS * PITCH) + rr * PITCH + skew(rr) + 16;
        } else {
            const int j  = k - CH * YROWS;
            const int cc = j >> 1;
            const int rr = j & 1;
            valid = true;
            src0 = reinterpret_cast<const char*>(
                x + (((size_t)(b * NC + cc) * NH + (i0 + rr)) * NW));
            dsto = cc * (TI * PITCH) + rr * PITCH + skew(rr);
        }
    }

    // Prologue: tid0 registers expected bytes for stages 0,1; owners issue.
    if (tid == 0) {
        mbar_expect(sm32 + 0, BYTES);
        mbar_expect(sm32 + 8, BYTES);
    }
    __syncthreads();   // expects registered before any completion can land
    if (valid) {
        bulk_g2s(sm32 + BUF0 + dsto, src0, ROWB, sm32 + 0);
        bulk_g2s(sm32 + BUF0 + BUF + dsto, src0 + STAGE_BYTES, ROWB, sm32 + 8);
    }

    // Accumulators: even dj -> 2 aligned col pairs each; odd dj -> 1 mid pair
    // + 2 scalar borders each.
    unsigned long long accE[5][2], accO[4];
    float sA[4], sB[4];
#pragma unroll
    for (int e = 0; e < 5; ++e) { accE[e][0] = 0ull; accE[e][1] = 0ull; }
#pragma unroll
    for (int o = 0; o < 4; ++o) { accO[o] = 0ull; sA[o] = 0.f; sB[o] = 0.f; }

    const int r = ti + di;   // y smem row 0..9
    const unsigned xoff = sm32 + BUF0 + (unsigned)(ti * PITCH) + skew(ti) + jg * 16;
    const unsigned yoff = sm32 + BUF0 + (unsigned)XAREA
                        + (unsigned)(r * PITCH) + skew(r) + jg * 16;

    for (int s = 0; s < NSTAGE; ++s) {
        const unsigned mb = sm32 + (unsigned)((s & 1) * 8);
        mbar_wait(mb, (unsigned)((s >> 1) & 1));
        if (tid == 0 && s + 2 < NSTAGE) mbar_expect(mb, BYTES);

        const unsigned bo = (unsigned)((s & 1) * BUF);
#pragma unroll 2
        for (int cc = 0; cc < CH; ++cc) {
            const unsigned xp = bo + (unsigned)(cc * (TI * PITCH)) + xoff;
            const unsigned yp = bo + (unsigned)(cc * (YROWS * PITCH)) + yoff;

            // X: 4 floats (2 aligned pairs). W: 12 floats (6 aligned pairs),
            // y window = cols jg*4-4 .. jg*4+7 (left pad at yp).
            unsigned long long X[2], W[6];
            lds2(xp, X[0], X[1]);
            lds2(yp,      W[0], W[1]);
            lds2(yp + 16, W[2], W[3]);
            lds2(yp + 32, W[4], W[5]);

            float x0, x1, x2, x3;
            upk(X[0], x0, x1); upk(X[1], x2, x3);
            const unsigned long long Sx = pk(x1, x2);

            // Even dj = 2e: pairs (c0,c1)->W[e], (c2,c3)->W[e+1].
#pragma unroll
            for (int e = 0; e < 5; ++e) {
                fma2(accE[e][0], X[0], W[e]);
                fma2(accE[e][1], X[1], W[e + 1]);
            }
            // Odd dj = 2o+1: mid pair (c1,c2)->W[o+1]; borders c0, c3.
#pragma unroll
            for (int o = 0; o < 4; ++o) {
                fma2(accO[o], Sx, W[o + 1]);
                float wl, wh, vl, vh;
                upk(W[o], wl, wh);        // wh = window float 2o+1
                upk(W[o + 2], vl, vh);    // vl = window float 2o+4
                sA[o] = fmaf(x0, wh, sA[o]);
                sB[o] = fmaf(x3, vl, sB[o]);
            }
        }

        __syncthreads();   // everyone finished reading buffer (s&1)
        if (valid && s + 2 < NSTAGE) {
            bulk_g2s(sm32 + BUF0 + (unsigned)((s & 1) * BUF) + dsto,
                     src0 + (size_t)(s + 2) * STAGE_BYTES, ROWB, mb);
        }
    }

    // ---- epilogue: scale by 1/C and store (4 cols per thread) ----
    const float sc = 1.0f / (float)NC;
    float* obase = out + (((size_t)b * (NP * NP) + (size_t)di * NP) * NH
                          + (i0 + ti)) * NW + jg * 4;
#pragma unroll
    for (int e = 0; e < 5; ++e) {          // dj = 2e
        float4 v;
        upk(accE[e][0], v.x, v.y);
        upk(accE[e][1], v.z, v.w);
        v.x *= sc; v.y *= sc; v.z *= sc; v.w *= sc;
        *reinterpret_cast<float4*>(obase + (size_t)(2 * e) * NH * NW) = v;
    }
#pragma unroll
    for (int o = 0; o < 4; ++o) {          // dj = 2o+1
        float f1, f2;
        upk(accO[o], f1, f2);
        float4 v;
        v.x = sA[o] * sc; v.y = f1 * sc; v.z = f2 * sc; v.w = sB[o] * sc;
        *reinterpret_cast<float4*>(obase + (size_t)(2 * o + 1) * NH * NW) = v;
    }
}

extern "C" void kernel_launch(void* const* d_in, const int* in_sizes, int n_in,
                              void* d_out, int out_size) {
    const float* x = (const float*)d_in[0];
    const float* y = (const float*)d_in[1];
    float* out = (float*)d_out;
    (void)in_sizes; (void)n_in; (void)out_size;

    cudaFuncSetAttribute(corr_kernel,
                         cudaFuncAttributeMaxDynamicSharedMemorySize, SMEM_TOTAL);

    dim3 grid(NH / TI, NB);   // (32, 16) = 512 blocks, 3 CTAs/SM
    corr_kernel<<<grid, NTHREADS, SMEM_TOTAL>>>(x, y, out);
}